// round 15
// baseline (speedup 1.0000x reference)
#include <cuda_runtime.h>
#include <cuda_fp16.h>
#include <cstdint>

#define E_EDGES 50000
#define EPAD    50048          // 391 * 128
#define KFLAT   8192           // 128 (c) * 64 (i)
#define MTILES  391
#define BK      64             // fp16 K-elements per stage (128B rows)
#define NT      (KFLAT / BK)   // 128 k-tiles

typedef unsigned long long ull;

// fp16 scratch: A (per-edge bilinear input) and W^T
__device__ __half g_A[(size_t)EPAD * KFLAT];
__device__ __half g_W[(size_t)128 * KFLAT];   // [o][k], k = c*64+i

// ---------------- helpers ----------------
__device__ __forceinline__ uint32_t smem_u32(const void* p) {
    uint32_t a;
    asm("{ .reg .u64 t; cvta.to.shared.u64 t, %1; cvt.u32.u64 %0, t; }" : "=r"(a) : "l"(p));
    return a;
}
#define SWZ128(x) ((x) ^ (((x) >> 3) & 0x70))

__device__ __forceinline__ void cp16(uint32_t dst, const void* src) {
    asm volatile("cp.async.cg.shared.global [%0], [%1], 16;" :: "r"(dst), "l"(src));
}
#define CP_COMMIT() asm volatile("cp.async.commit_group;" ::: "memory")
#define CP_WAIT(n)  asm volatile("cp.async.wait_group %0;" :: "n"(n) : "memory")

__device__ __forceinline__ void ldmx4(uint32_t* d, uint32_t addr) {
    asm volatile("ldmatrix.sync.aligned.m8n8.x4.shared.b16 {%0,%1,%2,%3}, [%4];"
        : "=r"(d[0]), "=r"(d[1]), "=r"(d[2]), "=r"(d[3]) : "r"(addr));
}
__device__ __forceinline__ void mma16816(float* c, const uint32_t* a, const uint32_t* b) {
    asm volatile(
        "mma.sync.aligned.m16n8k16.row.col.f32.f16.f16.f32 "
        "{%0,%1,%2,%3}, {%4,%5,%6,%7}, {%8,%9}, {%0,%1,%2,%3};"
        : "+f"(c[0]), "+f"(c[1]), "+f"(c[2]), "+f"(c[3])
        : "r"(a[0]), "r"(a[1]), "r"(a[2]), "r"(a[3]), "r"(b[0]), "r"(b[1]));
}
__device__ __forceinline__ unsigned pack_ff(float a, float b) {
    __half2 t = __floats2half2_rn(a, b);
    return *reinterpret_cast<unsigned*>(&t);
}
__device__ __forceinline__ ull pack2(float lo, float hi) {
    ull r;
    asm("mov.b64 %0, {%1, %2};" : "=l"(r) : "f"(lo), "f"(hi));
    return r;
}
__device__ __forceinline__ void unpack2(ull v, float& lo, float& hi) {
    asm("mov.b64 {%0, %1}, %2;" : "=f"(lo), "=f"(hi) : "l"(v));
}
__device__ __forceinline__ void fma2(ull& d, ull a, ull b) {
    asm("fma.rn.f32x2 %0, %1, %2, %0;" : "+l"(d) : "l"(a), "l"(b));
}

// ---------------------------------------------------------------------------
// Kernel 0: W transpose to fp16.  g_W[o][c*64+i] = (half)W[c,i,o].
// ---------------------------------------------------------------------------
__global__ void __launch_bounds__(256) wsplit_kernel(const float* __restrict__ W) {
    const int c = blockIdx.x;
    const int tid = threadIdx.x;
    __shared__ __align__(16) float sW[64 * 128];   // [i][o]
    #pragma unroll
    for (int l = 0; l < 8; l++)
        ((float4*)sW)[tid + 256 * l] = ((const float4*)(W + (size_t)c * 8192))[tid + 256 * l];
    __syncthreads();

    const int o  = tid >> 1;
    const int i0 = (tid & 1) * 32;
    size_t base = (size_t)o * KFLAT + c * 64 + i0;
    #pragma unroll
    for (int g = 0; g < 4; g++) {
        float a[8];
        #pragma unroll
        for (int j = 0; j < 8; j++)
            a[j] = sW[(i0 + g * 8 + j) * 128 + o];
        uint4 vh = make_uint4(pack_ff(a[0],a[1]), pack_ff(a[2],a[3]),
                              pack_ff(a[4],a[5]), pack_ff(a[6],a[7]));
        *(uint4*)&g_W[base + g * 8] = vh;
    }
}

// ---------------------------------------------------------------------------
// Kernel 1: prep v3 fixed — 2 edges per CTA, packed f32x2 A-phase.
// P stored transposed in smem: s_P2[e][kk][i] so adjacent i form f32x2 pairs.
// A[e,i,c] = sum_kk P[e,i,kk] * m[e*8+kk, c]; thread owns (edge, c), full
// 64-i row -> 128B contiguous stores.
// ---------------------------------------------------------------------------
__global__ void __launch_bounds__(256) prep_kernel(
    const float* __restrict__ rbf,   // (E, 64, 16)
    const float* __restrict__ sph,   // (E, 16, 16)
    const float* __restrict__ m)     // (E*8, 128)
{
    const int blk = blockIdx.x;
    const int tid = threadIdx.x;
    const int e_loc = tid >> 7;          // 0/1
    const int c     = tid & 127;
    const int e     = blk * 2 + e_loc;

    if (blk >= E_EDGES / 2) {
        uint4 z = make_uint4(0, 0, 0, 0);
        uint4* dst = (uint4*)&g_A[(size_t)e * KFLAT + c * 64];
        #pragma unroll
        for (int q = 0; q < 8; q++) dst[q] = z;
        return;
    }

    __shared__ __align__(16) float s_rbf[2048];   // [e][i][s]
    __shared__ __align__(16) float s_m[2048];     // [e][kk][c]
    __shared__ __align__(16) float s_sph[256];    // [e][s][kk]
    __shared__ __align__(16) float s_P2[1024];    // [e][kk][i]  (transposed)

    ((float4*)s_rbf)[tid]       = ((const float4*)(rbf + (size_t)blk * 2048))[tid];
    ((float4*)s_rbf)[tid + 256] = ((const float4*)(rbf + (size_t)blk * 2048))[tid + 256];
    ((float4*)s_m)[tid]         = ((const float4*)(m   + (size_t)blk * 2048))[tid];
    ((float4*)s_m)[tid + 256]   = ((const float4*)(m   + (size_t)blk * 2048))[tid + 256];
    {
        int el = tid >> 7, rest = tid & 127;
        int s = rest >> 3, kk = rest & 7;
        s_sph[el * 128 + rest] = sph[(size_t)(blk * 2 + el) * 256 + s * 16 + kk];
    }
    __syncthreads();

    // P: 1024 values, 4 per thread; store transposed [e][kk][i]
    #pragma unroll
    for (int rq = 0; rq < 4; rq++) {
        int o = tid + 256 * rq;
        int el = o >> 9, idx = o & 511;
        int i = idx >> 3, kk = idx & 7;
        float acc = 0.f;
        #pragma unroll
        for (int s = 0; s < 16; s++)
            acc += s_rbf[el * 1024 + i * 16 + s] * s_sph[el * 128 + s * 8 + kk];
        s_P2[el * 512 + kk * 64 + i] = acc;
    }
    __syncthreads();

    // A phase: packed f32x2.  acc2[j] = (A[2j], A[2j+1]) over i (j = 0..31).
    ull mc2[8];
    #pragma unroll
    for (int kk = 0; kk < 8; kk++) {
        float v = s_m[e_loc * 1024 + kk * 128 + c];
        mc2[kk] = pack2(v, v);
    }

    ull acc2[32];
    #pragma unroll
    for (int j = 0; j < 32; j++) acc2[j] = 0ull;

    const char* Pbase = (const char*)(s_P2 + e_loc * 512);
    #pragma unroll
    for (int kk = 0; kk < 8; kk++) {
        const ulonglong2* Prow = (const ulonglong2*)(Pbase + kk * 256);
        #pragma unroll
        for (int q = 0; q < 16; q++) {        // 16 x 16B = full 64-float row
            ulonglong2 p = Prow[q];           // i-pairs (4q,4q+1) and (4q+2,4q+3)
            fma2(acc2[2 * q],     p.x, mc2[kk]);
            fma2(acc2[2 * q + 1], p.y, mc2[kk]);
        }
    }

    uint4* dst = (uint4*)&g_A[(size_t)e * KFLAT + c * 64];
    #pragma unroll
    for (int g = 0; g < 4; g++) {
        unsigned h2[8];
        #pragma unroll
        for (int p = 0; p < 8; p++) {
            float f0, f1;
            unpack2(acc2[g * 8 + p], f0, f1);
            h2[p] = pack_ff(f0, f1);
        }
        dst[g * 2]     = make_uint4(h2[0], h2[1], h2[2], h2[3]);
        dst[g * 2 + 1] = make_uint4(h2[4], h2[5], h2[6], h2[7]);
    }
}

// ---------------------------------------------------------------------------
// Kernel 2: single-pass fp16 HMMA GEMM, 3-stage cp.async ring, one sync per
// k-tile (R10 proven form).  out[E,128] = A[E,8192] @ W^T.
// CTA tile 128x128, BK=64, 8 warps (2x4), warp tile 64x32, 2 CTAs/SM.
// ---------------------------------------------------------------------------
#define OFF_A 0
#define OFF_B 16384
#define STAGE_BYTES 32768
#define NSTAGE 3
#define SMEM_TOTAL_GEMM (NSTAGE * STAGE_BYTES)

__global__ void __launch_bounds__(256, 2) gemm_kernel(float* __restrict__ out) {
    extern __shared__ char smem[];
    const uint32_t sbase = smem_u32(smem);
    const int tid  = threadIdx.x;
    const int wid  = tid >> 5, lane = tid & 31;
    const int warp_m = wid >> 2;        // 0..1 -> 64-row slab
    const int warp_n = wid & 3;         // 0..3 -> 32-col slab
    const int m_base = blockIdx.x * 128;

    // ---- staging: thread -> one 128B row (tid<128: A row, else W row) ----
    const int r = tid & 127;
    const char* gsrc = (tid < 128)
        ? (const char*)g_A + (size_t)(m_base + r) * (KFLAT * 2)
        : (const char*)g_W + (size_t)r * (KFLAT * 2);
    const uint32_t soff = (tid < 128) ? OFF_A : OFF_B;
    uint32_t swz[8];
    #pragma unroll
    for (int q = 0; q < 8; q++) swz[q] = soff + SWZ128(r * 128 + q * 16);

    auto load_stage = [&](int t, int st) {
        const uint32_t su = sbase + st * STAGE_BYTES;
        const size_t koff = (size_t)t * 128;
        #pragma unroll
        for (int q = 0; q < 8; q++)
            cp16(su + swz[q], gsrc + koff + q * 16);
    };

    // ---- ldmatrix per-thread byte offsets ----
    uint32_t aoff[4];
    #pragma unroll
    for (int mt = 0; mt < 4; mt++)
        aoff[mt] = (warp_m * 64 + mt * 16 + (lane & 15)) * 128 + (lane >> 4) * 16;
    uint32_t boff[2];
    #pragma unroll
    for (int p = 0; p < 2; p++) {
        int g = lane >> 3;
        int n = warp_n * 32 + (2 * p + (g >> 1)) * 8 + (lane & 7);
        boff[p] = n * 128 + (g & 1) * 16;
    }

    float acc[4][4][4];
    #pragma unroll
    for (int mt = 0; mt < 4; mt++)
        #pragma unroll
        for (int nt = 0; nt < 4; nt++)
            #pragma unroll
            for (int q = 0; q < 4; q++) acc[mt][nt][q] = 0.f;

    load_stage(0, 0); CP_COMMIT();
    load_stage(1, 1); CP_COMMIT();

    int st = 0;
    #pragma unroll 1
    for (int t = 0; t < NT; t++) {
        if (t == NT - 1) { CP_WAIT(0); } else { CP_WAIT(1); }
        __syncthreads();
        if (t + 2 < NT) {
            int st2 = st + 2; if (st2 >= NSTAGE) st2 -= NSTAGE;
            load_stage(t + 2, st2);
            CP_COMMIT();
        }

        const uint32_t su = sbase + st * STAGE_BYTES;
        #pragma unroll
        for (int ks = 0; ks < 4; ks++) {
            const int kb = ks * 32;
            uint32_t ah[4][4], bh[4][2];
            #pragma unroll
            for (int mt = 0; mt < 4; mt++)
                ldmx4(ah[mt], su + OFF_A + SWZ128(aoff[mt] + kb));
            #pragma unroll
            for (int p = 0; p < 2; p++) {
                uint32_t b4[4];
                ldmx4(b4, su + OFF_B + SWZ128(boff[p] + kb));
                bh[2*p][0] = b4[0]; bh[2*p][1] = b4[1];
                bh[2*p+1][0] = b4[2]; bh[2*p+1][1] = b4[3];
            }
            #pragma unroll
            for (int mt = 0; mt < 4; mt++)
                #pragma unroll
                for (int nt = 0; nt < 4; nt++)
                    mma16816(acc[mt][nt], ah[mt], bh[nt]);
        }

        if (++st >= NSTAGE) st = 0;
    }

    // ---- epilogue ----
    #pragma unroll
    for (int mt = 0; mt < 4; mt++) {
        const int row0 = m_base + warp_m * 64 + mt * 16 + (lane >> 2);
        #pragma unroll
        for (int nt = 0; nt < 4; nt++) {
            const int col = warp_n * 32 + nt * 8 + (lane & 3) * 2;
            if (row0 < E_EDGES)
                *(float2*)&out[(size_t)row0 * 128 + col] =
                    make_float2(acc[mt][nt][0], acc[mt][nt][1]);
            if (row0 + 8 < E_EDGES)
                *(float2*)&out[(size_t)(row0 + 8) * 128 + col] =
                    make_float2(acc[mt][nt][2], acc[mt][nt][3]);
        }
    }
}

// ---------------------------------------------------------------------------
extern "C" void kernel_launch(void* const* d_in, const int* in_sizes, int n_in,
                              void* d_out, int out_size) {
    const float* rbf = (const float*)d_in[0];   // (E, 64, 16)
    const float* sph = (const float*)d_in[1];   // (E, 16, 16)
    const float* m   = (const float*)d_in[2];   // (E*8, 128)
    const float* w   = (const float*)d_in[3];   // (128, 64, 128)
    float* out = (float*)d_out;

    cudaFuncSetAttribute(gemm_kernel, cudaFuncAttributeMaxDynamicSharedMemorySize, SMEM_TOTAL_GEMM);

    wsplit_kernel<<<128, 256>>>(w);
    prep_kernel<<<EPAD / 2, 256>>>(rbf, sph, m);
    gemm_kernel<<<MTILES, 256, SMEM_TOTAL_GEMM>>>(out);
}

// round 17
// speedup vs baseline: 1.5619x; 1.5619x over previous
#include <cuda_runtime.h>
#include <cuda_fp16.h>
#include <cstdint>

#define E_EDGES 50000
#define EPAD    50048          // 391 * 128
#define KFLAT   8192           // 128 (c) * 64 (i)
#define MTILES  391
#define NT      128            // k-tiles (BK = 64 halfs = 128B rows)

// Tiled, pre-swizzled stage images:
//   g_A: [mtile(391)][ktile(128)][row e&127][128B]   (row chunks q^(e&7))
//   g_W: [ktile(128)][row o][128B]                   (row chunks q^(o&7))
__device__ __half g_A[(size_t)EPAD * KFLAT];
__device__ __half g_W[(size_t)128 * KFLAT];

// ---------------- helpers ----------------
__device__ __forceinline__ uint32_t smem_u32(const void* p) {
    uint32_t a;
    asm("{ .reg .u64 t; cvta.to.shared.u64 t, %1; cvt.u32.u64 %0, t; }" : "=r"(a) : "l"(p));
    return a;
}
#define SWZ128(x) ((x) ^ (((x) >> 3) & 0x70))

__device__ __forceinline__ void bulkcp(uint32_t dst, const void* src, uint32_t bytes, uint32_t mbar) {
    asm volatile("cp.async.bulk.shared::cta.global.mbarrier::complete_tx::bytes [%0], [%1], %2, [%3];"
        :: "r"(dst), "l"(src), "r"(bytes), "r"(mbar) : "memory");
}
__device__ __forceinline__ void mbar_init(uint32_t mbar, uint32_t cnt) {
    asm volatile("mbarrier.init.shared.b64 [%0], %1;" :: "r"(mbar), "r"(cnt) : "memory");
}
__device__ __forceinline__ void mbar_expect(uint32_t mbar, uint32_t bytes) {
    asm volatile("mbarrier.arrive.expect_tx.shared.b64 _, [%0], %1;" :: "r"(mbar), "r"(bytes) : "memory");
}
__device__ __forceinline__ void mbar_wait(uint32_t mbar, uint32_t parity) {
    asm volatile(
        "{\n\t.reg .pred P;\n\t"
        "W_%=:\n\t"
        "mbarrier.try_wait.parity.acquire.cta.shared::cta.b64 P, [%0], %1;\n\t"
        "@P bra.uni D_%=;\n\t"
        "bra.uni W_%=;\n\t"
        "D_%=:\n\t}"
        :: "r"(mbar), "r"(parity) : "memory");
}
#define FENCE_ASYNC() asm volatile("fence.proxy.async.shared::cta;" ::: "memory")

__device__ __forceinline__ void ldmx4(uint32_t* d, uint32_t addr) {
    asm volatile("ldmatrix.sync.aligned.m8n8.x4.shared.b16 {%0,%1,%2,%3}, [%4];"
        : "=r"(d[0]), "=r"(d[1]), "=r"(d[2]), "=r"(d[3]) : "r"(addr));
}
__device__ __forceinline__ void mma16816(float* c, const uint32_t* a, const uint32_t* b) {
    asm volatile(
        "mma.sync.aligned.m16n8k16.row.col.f32.f16.f16.f32 "
        "{%0,%1,%2,%3}, {%4,%5,%6,%7}, {%8,%9}, {%0,%1,%2,%3};"
        : "+f"(c[0]), "+f"(c[1]), "+f"(c[2]), "+f"(c[3])
        : "r"(a[0]), "r"(a[1]), "r"(a[2]), "r"(a[3]), "r"(b[0]), "r"(b[1]));
}
__device__ __forceinline__ unsigned pack_ff(float a, float b) {
    __half2 t = __floats2half2_rn(a, b);
    return *reinterpret_cast<unsigned*>(&t);
}

// ---------------------------------------------------------------------------
// Kernel 0: W transpose to fp16, tiled + pre-swizzled stage layout.
// Tile t = c (blockIdx).  Row o holds W[c*64 + i][o] for i=0..63.
// ---------------------------------------------------------------------------
__global__ void __launch_bounds__(256) wsplit_kernel(const float* __restrict__ W) {
    const int c = blockIdx.x;
    const int tid = threadIdx.x;
    __shared__ __align__(16) float sW[64 * 128];   // [i][o]
    #pragma unroll
    for (int l = 0; l < 8; l++)
        ((float4*)sW)[tid + 256 * l] = ((const float4*)(W + (size_t)c * 8192))[tid + 256 * l];
    __syncthreads();

    const int o  = tid >> 1;
    const int i0 = (tid & 1) * 32;
    const int key = o & 7;
    uint4* rowp = (uint4*)((char*)g_W + (size_t)c * 16384 + (size_t)o * 128);
    #pragma unroll
    for (int g = 0; g < 4; g++) {
        float a[8];
        #pragma unroll
        for (int j = 0; j < 8; j++)
            a[j] = sW[(i0 + g * 8 + j) * 128 + o];
        uint4 vh = make_uint4(pack_ff(a[0],a[1]), pack_ff(a[2],a[3]),
                              pack_ff(a[4],a[5]), pack_ff(a[6],a[7]));
        rowp[((i0 >> 3) + g) ^ key] = vh;
    }
}

// ---------------------------------------------------------------------------
// Kernel 1: prep (R10-proven scalar form), tiled + pre-swizzled A stores.
// 2 edges per CTA; thread owns (edge, channel c) = one 128B stage row.
// A[e,i,c] = sum_kk P[e,i,kk] * m[e*8+kk, c],  P = rbf @ sph[:, :8].
// ---------------------------------------------------------------------------
__global__ void __launch_bounds__(256) prep_kernel(
    const float* __restrict__ rbf,   // (E, 64, 16)
    const float* __restrict__ sph,   // (E, 16, 16)
    const float* __restrict__ m)     // (E*8, 128)
{
    const int blk = blockIdx.x;
    const int tid = threadIdx.x;
    const int e_loc = tid >> 7;          // 0/1
    const int c     = tid & 127;
    const int e     = blk * 2 + e_loc;

    uint4* rowp = (uint4*)((char*)g_A
        + ((size_t)(e >> 7) * 128 + c) * 16384 + (size_t)(e & 127) * 128);

    if (blk >= E_EDGES / 2) {
        uint4 z = make_uint4(0, 0, 0, 0);
        #pragma unroll
        for (int q = 0; q < 8; q++) rowp[q] = z;
        return;
    }

    __shared__ __align__(16) float s_rbf[2048];   // [e][i][s]
    __shared__ __align__(16) float s_m[2048];     // [e][kk][c]
    __shared__ __align__(16) float s_sph[256];    // [e][s][kk]
    __shared__ __align__(16) float s_P[1024];     // [e][i][kk]

    ((float4*)s_rbf)[tid]       = ((const float4*)(rbf + (size_t)blk * 2048))[tid];
    ((float4*)s_rbf)[tid + 256] = ((const float4*)(rbf + (size_t)blk * 2048))[tid + 256];
    ((float4*)s_m)[tid]         = ((const float4*)(m   + (size_t)blk * 2048))[tid];
    ((float4*)s_m)[tid + 256]   = ((const float4*)(m   + (size_t)blk * 2048))[tid + 256];
    {
        int el = tid >> 7, rest = tid & 127;
        int s = rest >> 3, kk = rest & 7;
        s_sph[el * 128 + rest] = sph[(size_t)(blk * 2 + el) * 256 + s * 16 + kk];
    }
    __syncthreads();

    #pragma unroll
    for (int rq = 0; rq < 4; rq++) {
        int o = tid + 256 * rq;
        int el = o >> 9, idx = o & 511;
        int i = idx >> 3, kk = idx & 7;
        float acc = 0.f;
        #pragma unroll
        for (int s = 0; s < 16; s++)
            acc += s_rbf[el * 1024 + i * 16 + s] * s_sph[el * 128 + s * 8 + kk];
        s_P[o] = acc;
    }
    __syncthreads();

    float mc[8];
    #pragma unroll
    for (int kk = 0; kk < 8; kk++) mc[kk] = s_m[e_loc * 1024 + kk * 128 + c];

    const float* Pe = s_P + e_loc * 512;
    const int key = e & 7;
    #pragma unroll
    for (int g = 0; g < 4; g++) {
        float a[16];
        #pragma unroll
        for (int j = 0; j < 16; j++) {
            int i = g * 16 + j;
            float acc = 0.f;
            #pragma unroll
            for (int kk = 0; kk < 8; kk++)
                acc += Pe[i * 8 + kk] * mc[kk];
            a[j] = acc;
        }
        uint4 v0 = make_uint4(pack_ff(a[0],a[1]),  pack_ff(a[2],a[3]),
                              pack_ff(a[4],a[5]),  pack_ff(a[6],a[7]));
        uint4 v1 = make_uint4(pack_ff(a[8],a[9]),  pack_ff(a[10],a[11]),
                              pack_ff(a[12],a[13]), pack_ff(a[14],a[15]));
        rowp[(2 * g) ^ key]     = v0;
        rowp[(2 * g + 1) ^ key] = v1;
    }
}

// ---------------------------------------------------------------------------
// Kernel 2: single-pass fp16 HMMA GEMM with BULK-COPY staging.
// Per k-tile: thread0 issues expect_tx + 2x cp.async.bulk (16KB A, 16KB B)
// into a 3-stage mbarrier ring.  LDGSTS count per tile: 2048 -> 2.
// CTA tile 128x128, 8 warps (2x4), warp tile 64x32, 2 CTAs/SM.
// ---------------------------------------------------------------------------
#define OFF_B 16384
#define STAGE_BYTES 32768
#define NSTAGE 3
#define MBAR_OFF (NSTAGE * STAGE_BYTES)
#define SMEM_TOTAL_GEMM (MBAR_OFF + 64)

__global__ void __launch_bounds__(256, 2) gemm_kernel(float* __restrict__ out) {
    extern __shared__ char smem[];
    const uint32_t sbase = smem_u32(smem);
    const int tid  = threadIdx.x;
    const int wid  = tid >> 5, lane = tid & 31;
    const int warp_m = wid >> 2;        // 0..1 -> 64-row slab
    const int warp_n = wid & 3;         // 0..3 -> 32-col slab
    const int m_base = blockIdx.x * 128;

    const char* Abase = (const char*)g_A + (size_t)blockIdx.x * 128 * 16384;
    const char* Bbase = (const char*)g_W;

    if (tid == 0) {
        #pragma unroll
        for (int s = 0; s < NSTAGE; s++)
            mbar_init(sbase + MBAR_OFF + s * 8, 1);
    }
    __syncthreads();
    FENCE_ASYNC();

    auto issue = [&](int t, int s) {
        const uint32_t mb = sbase + MBAR_OFF + s * 8;
        const uint32_t su = sbase + s * STAGE_BYTES;
        mbar_expect(mb, 2 * 16384u);
        bulkcp(su,         Abase + (size_t)t * 16384, 16384u, mb);
        bulkcp(su + OFF_B, Bbase + (size_t)t * 16384, 16384u, mb);
    };
    if (tid == 0) { issue(0, 0); issue(1, 1); }

    // ---- ldmatrix per-thread byte offsets (tile-local; swizzle at use) ----
    uint32_t aoff[4];
    #pragma unroll
    for (int mt = 0; mt < 4; mt++)
        aoff[mt] = (warp_m * 64 + mt * 16 + (lane & 15)) * 128 + (lane >> 4) * 16;
    uint32_t boff[2];
    #pragma unroll
    for (int p = 0; p < 2; p++) {
        int g = lane >> 3;
        int n = warp_n * 32 + (2 * p + (g >> 1)) * 8 + (lane & 7);
        boff[p] = n * 128 + (g & 1) * 16;
    }

    float acc[4][4][4];
    #pragma unroll
    for (int mt = 0; mt < 4; mt++)
        #pragma unroll
        for (int nt = 0; nt < 4; nt++)
            #pragma unroll
            for (int q = 0; q < 4; q++) acc[mt][nt][q] = 0.f;

    int st = 0;
    #pragma unroll 1
    for (int t = 0; t < NT; t++) {
        mbar_wait(sbase + MBAR_OFF + st * 8, (uint32_t)((t / 3) & 1));

        const uint32_t su = sbase + st * STAGE_BYTES;
        #pragma unroll
        for (int ks = 0; ks < 4; ks++) {
            const int kb = ks * 32;
            uint32_t ah[4][4], bh[4][2];
            #pragma unroll
            for (int mt = 0; mt < 4; mt++)
                ldmx4(ah[mt], su + SWZ128(aoff[mt] + kb));
            #pragma unroll
            for (int p = 0; p < 2; p++) {
                uint32_t b4[4];
                ldmx4(b4, su + OFF_B + SWZ128(boff[p] + kb));
                bh[2*p][0] = b4[0]; bh[2*p][1] = b4[1];
                bh[2*p+1][0] = b4[2]; bh[2*p+1][1] = b4[3];
            }
            #pragma unroll
            for (int mt = 0; mt < 4; mt++)
                #pragma unroll
                for (int nt = 0; nt < 4; nt++)
                    mma16816(acc[mt][nt], ah[mt], bh[nt]);
        }

        __syncthreads();   // all threads done reading stage used at t-1
        if (t + 2 < NT && tid == 0) {
            int s2 = st + 2; if (s2 >= NSTAGE) s2 -= NSTAGE;
            issue(t + 2, s2);
        }
        if (++st >= NSTAGE) st = 0;
    }

    // ---- epilogue ----
    #pragma unroll
    for (int mt = 0; mt < 4; mt++) {
        const int row0 = m_base + warp_m * 64 + mt * 16 + (lane >> 2);
        #pragma unroll
        for (int nt = 0; nt < 4; nt++) {
            const int col = warp_n * 32 + nt * 8 + (lane & 3) * 2;
            if (row0 < E_EDGES)
                *(float2*)&out[(size_t)row0 * 128 + col] =
                    make_float2(acc[mt][nt][0], acc[mt][nt][1]);
            if (row0 + 8 < E_EDGES)
                *(float2*)&out[(size_t)(row0 + 8) * 128 + col] =
                    make_float2(acc[mt][nt][2], acc[mt][nt][3]);
        }
    }
}

// ---------------------------------------------------------------------------
extern "C" void kernel_launch(void* const* d_in, const int* in_sizes, int n_in,
                              void* d_out, int out_size) {
    const float* rbf = (const float*)d_in[0];   // (E, 64, 16)
    const float* sph = (const float*)d_in[1];   // (E, 16, 16)
    const float* m   = (const float*)d_in[2];   // (E*8, 128)
    const float* w   = (const float*)d_in[3];   // (128, 64, 128)
    float* out = (float*)d_out;

    cudaFuncSetAttribute(gemm_kernel, cudaFuncAttributeMaxDynamicSharedMemorySize, SMEM_TOTAL_GEMM);

    wsplit_kernel<<<128, 256>>>(w);
    prep_kernel<<<EPAD / 2, 256>>>(rbf, sph, m);
    gemm_kernel<<<MTILES, 256, SMEM_TOTAL_GEMM>>>(out);
}